// round 1
// baseline (speedup 1.0000x reference)
#include <cuda_runtime.h>
#include <cstdint>
#include <cstddef>

// Problem constants
#define BATCH   4
#define SLEN    4096
#define DDIM    1024
#define MTOT    (BATCH * SLEN)          // 16384

// Scratch buffers (allocation-free rule: __device__ globals)
__device__ float g_Q[(size_t)BATCH * SLEN * DDIM];   // 64 MB
__device__ float g_K[(size_t)BATCH * SLEN * DDIM];   // 64 MB
__device__ float g_V[(size_t)BATCH * SLEN * DDIM];   // 64 MB
__device__ float g_S[(size_t)BATCH * SLEN * SLEN];   // 256 MB

// ---------------------------------------------------------------------------
// Tiled GEMM, NT form: C[m,n] = sum_k A[m,k] * B[n,k]
// BM=BN=128, BK=16, 256 threads, 8x8 per thread. All dims assumed divisible.
// blockIdx.z indexes batch via strides.
// ---------------------------------------------------------------------------
__global__ __launch_bounds__(256) void gemm_nt(
    const float* __restrict__ A, const float* __restrict__ B, float* __restrict__ C,
    int M, int N, int K, size_t sA, size_t sB, size_t sC)
{
    A += (size_t)blockIdx.z * sA;
    B += (size_t)blockIdx.z * sB;
    C += (size_t)blockIdx.z * sC;

    __shared__ float As[16][128];
    __shared__ float Bs[16][128];

    const int tid = threadIdx.x;
    const int tx  = tid & 15;        // 0..15 -> N direction
    const int ty  = tid >> 4;        // 0..15 -> M direction
    const int bm  = blockIdx.y * 128;
    const int bn  = blockIdx.x * 128;

    // load mapping: 128 rows x 16 cols per tile; each thread: 2 float4
    const int lr = tid >> 2;         // 0..63
    const int lc = (tid & 3) << 2;   // 0,4,8,12

    const float* Aptr = A + (size_t)(bm + lr) * K + lc;
    const float* Bptr = B + (size_t)(bn + lr) * K + lc;

    float acc[8][8];
    #pragma unroll
    for (int i = 0; i < 8; i++)
        #pragma unroll
        for (int j = 0; j < 8; j++) acc[i][j] = 0.0f;

    for (int k0 = 0; k0 < K; k0 += 16) {
        float4 a0 = *(const float4*)(Aptr + k0);
        float4 a1 = *(const float4*)(Aptr + (size_t)64 * K + k0);
        float4 b0 = *(const float4*)(Bptr + k0);
        float4 b1 = *(const float4*)(Bptr + (size_t)64 * K + k0);

        As[lc + 0][lr]      = a0.x; As[lc + 1][lr]      = a0.y;
        As[lc + 2][lr]      = a0.z; As[lc + 3][lr]      = a0.w;
        As[lc + 0][lr + 64] = a1.x; As[lc + 1][lr + 64] = a1.y;
        As[lc + 2][lr + 64] = a1.z; As[lc + 3][lr + 64] = a1.w;

        Bs[lc + 0][lr]      = b0.x; Bs[lc + 1][lr]      = b0.y;
        Bs[lc + 2][lr]      = b0.z; Bs[lc + 3][lr]      = b0.w;
        Bs[lc + 0][lr + 64] = b1.x; Bs[lc + 1][lr + 64] = b1.y;
        Bs[lc + 2][lr + 64] = b1.z; Bs[lc + 3][lr + 64] = b1.w;

        __syncthreads();

        #pragma unroll
        for (int k = 0; k < 16; k++) {
            float a[8], b[8];
            *(float4*)(a)     = *(const float4*)&As[k][ty * 8];
            *(float4*)(a + 4) = *(const float4*)&As[k][ty * 8 + 4];
            *(float4*)(b)     = *(const float4*)&Bs[k][tx * 8];
            *(float4*)(b + 4) = *(const float4*)&Bs[k][tx * 8 + 4];
            #pragma unroll
            for (int i = 0; i < 8; i++)
                #pragma unroll
                for (int j = 0; j < 8; j++)
                    acc[i][j] += a[i] * b[j];
        }
        __syncthreads();
    }

    #pragma unroll
    for (int i = 0; i < 8; i++) {
        float* Crow = C + (size_t)(bm + ty * 8 + i) * N + bn + tx * 8;
        *(float4*)(Crow)     = make_float4(acc[i][0], acc[i][1], acc[i][2], acc[i][3]);
        *(float4*)(Crow + 4) = make_float4(acc[i][4], acc[i][5], acc[i][6], acc[i][7]);
    }
}

// ---------------------------------------------------------------------------
// Tiled GEMM, NN form: C[m,n] = sum_k A[m,k] * B[k,n]
// ---------------------------------------------------------------------------
__global__ __launch_bounds__(256) void gemm_nn(
    const float* __restrict__ A, const float* __restrict__ B, float* __restrict__ C,
    int M, int N, int K, size_t sA, size_t sB, size_t sC)
{
    A += (size_t)blockIdx.z * sA;
    B += (size_t)blockIdx.z * sB;
    C += (size_t)blockIdx.z * sC;

    __shared__ float As[16][128];
    __shared__ float Bs[16][128];

    const int tid = threadIdx.x;
    const int tx  = tid & 15;
    const int ty  = tid >> 4;
    const int bm  = blockIdx.y * 128;
    const int bn  = blockIdx.x * 128;

    // A tile: 128 rows x 16 k (transpose into As)
    const int lr = tid >> 2;
    const int lc = (tid & 3) << 2;
    const float* Aptr = A + (size_t)(bm + lr) * K + lc;

    // B tile: 16 k-rows x 128 n-cols (direct copy)
    const int br = tid >> 5;          // 0..7
    const int bc = (tid & 31) << 2;   // 0..124

    float acc[8][8];
    #pragma unroll
    for (int i = 0; i < 8; i++)
        #pragma unroll
        for (int j = 0; j < 8; j++) acc[i][j] = 0.0f;

    for (int k0 = 0; k0 < K; k0 += 16) {
        float4 a0 = *(const float4*)(Aptr + k0);
        float4 a1 = *(const float4*)(Aptr + (size_t)64 * K + k0);
        float4 v0 = *(const float4*)(B + (size_t)(k0 + br) * N + bn + bc);
        float4 v1 = *(const float4*)(B + (size_t)(k0 + br + 8) * N + bn + bc);

        As[lc + 0][lr]      = a0.x; As[lc + 1][lr]      = a0.y;
        As[lc + 2][lr]      = a0.z; As[lc + 3][lr]      = a0.w;
        As[lc + 0][lr + 64] = a1.x; As[lc + 1][lr + 64] = a1.y;
        As[lc + 2][lr + 64] = a1.z; As[lc + 3][lr + 64] = a1.w;

        *(float4*)&Bs[br][bc]     = v0;
        *(float4*)&Bs[br + 8][bc] = v1;

        __syncthreads();

        #pragma unroll
        for (int k = 0; k < 16; k++) {
            float a[8], b[8];
            *(float4*)(a)     = *(const float4*)&As[k][ty * 8];
            *(float4*)(a + 4) = *(const float4*)&As[k][ty * 8 + 4];
            *(float4*)(b)     = *(const float4*)&Bs[k][tx * 8];
            *(float4*)(b + 4) = *(const float4*)&Bs[k][tx * 8 + 4];
            #pragma unroll
            for (int i = 0; i < 8; i++)
                #pragma unroll
                for (int j = 0; j < 8; j++)
                    acc[i][j] += a[i] * b[j];
        }
        __syncthreads();
    }

    #pragma unroll
    for (int i = 0; i < 8; i++) {
        float* Crow = C + (size_t)(bm + ty * 8 + i) * N + bn + tx * 8;
        *(float4*)(Crow)     = make_float4(acc[i][0], acc[i][1], acc[i][2], acc[i][3]);
        *(float4*)(Crow + 4) = make_float4(acc[i][4], acc[i][5], acc[i][6], acc[i][7]);
    }
}

// ---------------------------------------------------------------------------
// Row softmax over 4096 columns. One block (256 threads) per row.
// ---------------------------------------------------------------------------
__global__ __launch_bounds__(256) void softmax_kernel(float* __restrict__ Sm)
{
    float* row = Sm + (size_t)blockIdx.x * SLEN;
    const int t    = threadIdx.x;
    const int lane = t & 31;
    const int warp = t >> 5;

    __shared__ float red[8];

    float v[16];
    float mx = -1e30f;
    #pragma unroll
    for (int i = 0; i < 16; i++) {
        v[i] = row[t + (i << 8)];
        mx = fmaxf(mx, v[i]);
    }
    #pragma unroll
    for (int o = 16; o > 0; o >>= 1)
        mx = fmaxf(mx, __shfl_xor_sync(0xffffffffu, mx, o));
    if (lane == 0) red[warp] = mx;
    __syncthreads();
    float rmax = red[0];
    #pragma unroll
    for (int i = 1; i < 8; i++) rmax = fmaxf(rmax, red[i]);

    float sum = 0.0f;
    #pragma unroll
    for (int i = 0; i < 16; i++) {
        v[i] = __expf(v[i] - rmax);
        sum += v[i];
    }
    #pragma unroll
    for (int o = 16; o > 0; o >>= 1)
        sum += __shfl_xor_sync(0xffffffffu, sum, o);
    __syncthreads();                // red[] reads for max are done
    if (lane == 0) red[warp] = sum;
    __syncthreads();
    float rsum = 0.0f;
    #pragma unroll
    for (int i = 0; i < 8; i++) rsum += red[i];

    const float inv = 1.0f / rsum;
    #pragma unroll
    for (int i = 0; i < 16; i++)
        row[t + (i << 8)] = v[i] * inv;
}

// ---------------------------------------------------------------------------
// Epilogue: y = attended + x;  out = y / ||y||_2 (per 1024-row).
// One block (256 threads) per row; out currently holds `attended`.
// ---------------------------------------------------------------------------
__global__ __launch_bounds__(256) void epilogue_kernel(
    const float* __restrict__ x, float* __restrict__ out)
{
    const size_t base = (size_t)blockIdx.x * DDIM;
    const int t    = threadIdx.x;
    const int lane = t & 31;
    const int warp = t >> 5;

    __shared__ float red[8];

    float4 a  = *(const float4*)(out + base + t * 4);
    float4 xv = *(const float4*)(x   + base + t * 4);
    float y0 = a.x + xv.x;
    float y1 = a.y + xv.y;
    float y2 = a.z + xv.z;
    float y3 = a.w + xv.w;

    float ss = y0 * y0 + y1 * y1 + y2 * y2 + y3 * y3;
    #pragma unroll
    for (int o = 16; o > 0; o >>= 1)
        ss += __shfl_xor_sync(0xffffffffu, ss, o);
    if (lane == 0) red[warp] = ss;
    __syncthreads();
    float tot = 0.0f;
    #pragma unroll
    for (int i = 0; i < 8; i++) tot += red[i];

    const float inv = 1.0f / sqrtf(tot);
    *(float4*)(out + base + t * 4) =
        make_float4(y0 * inv, y1 * inv, y2 * inv, y3 * inv);
}

// ---------------------------------------------------------------------------
// Launch
// ---------------------------------------------------------------------------
extern "C" void kernel_launch(void* const* d_in, const int* in_sizes, int n_in,
                              void* d_out, int out_size)
{
    const float* x  = (const float*)d_in[0];
    const float* Wq = (const float*)d_in[1];
    const float* Wk = (const float*)d_in[2];
    const float* Wv = (const float*)d_in[3];
    float* out = (float*)d_out;

    float *Q, *K, *V, *Sc;
    cudaGetSymbolAddress((void**)&Q,  g_Q);
    cudaGetSymbolAddress((void**)&K,  g_K);
    cudaGetSymbolAddress((void**)&V,  g_V);
    cudaGetSymbolAddress((void**)&Sc, g_S);

    const size_t sQKV = (size_t)SLEN * DDIM;   // per-batch stride in Q/K/V
    const size_t sSS  = (size_t)SLEN * SLEN;   // per-batch stride in scores

    dim3 blk(256);

    // QKV projections: [16384,1024] = x[16384,1024] @ W^T   (NT)
    dim3 gqkv(DDIM / 128, MTOT / 128, 1);      // (8, 128, 1)
    gemm_nt<<<gqkv, blk>>>(x, Wq, Q, MTOT, DDIM, DDIM, 0, 0, 0);
    gemm_nt<<<gqkv, blk>>>(x, Wk, K, MTOT, DDIM, DDIM, 0, 0, 0);
    gemm_nt<<<gqkv, blk>>>(x, Wv, V, MTOT, DDIM, DDIM, 0, 0, 0);

    // scores = Q @ K^T per batch   (NT, batched over z)
    dim3 gsc(SLEN / 128, SLEN / 128, BATCH);   // (32, 32, 4)
    gemm_nt<<<gsc, blk>>>(Q, K, Sc, SLEN, SLEN, DDIM, sQKV, sQKV, sSS);

    // softmax over rows (BETA = 1)
    softmax_kernel<<<MTOT, blk>>>(Sc);

    // attended = P @ V per batch   (NN), written straight into d_out
    dim3 gav(DDIM / 128, SLEN / 128, BATCH);   // (8, 32, 4)
    gemm_nn<<<gav, blk>>>(Sc, V, out, SLEN, DDIM, SLEN, sSS, sQKV, sQKV);

    // y = attended + x; L2 normalize
    epilogue_kernel<<<MTOT, blk>>>(x, out);
}